// round 7
// baseline (speedup 1.0000x reference)
#include <cuda_runtime.h>
#include <math.h>

#define NUM_LEVELS 16
#define HASHMAP_SIZE (1u << 19)
#define HASH_MASK (HASHMAP_SIZE - 1u)
#define PRIME_Y 2654435761u
#define PRIME_Z 805459861u

struct Params {
    float scale[NUM_LEVELS];
    int   res[NUM_LEVELS];
    unsigned hashed;  // bitmask: level uses spatial hash
};

// ---------------- Kernel A: levels 2..15 (global gathers) ----------------
__global__ void __launch_bounds__(256) hashgrid_upper_kernel(
    const float* __restrict__ coords,
    const float2* __restrict__ table,
    float2* __restrict__ out,
    int n_points, Params P)
{
    long long total = (long long)n_points * NUM_LEVELS;
    long long tid = blockIdx.x * 256LL + threadIdx.x;
    if (tid >= total) return;

    int level = (int)(tid & (NUM_LEVELS - 1));
    if (level < 2) return;  // handled by lower kernel; lanes predicate off
    int p = (int)(tid >> 4);

    const float* cp = coords + (size_t)p * 3;
    float x = __ldg(cp + 0);
    float y = __ldg(cp + 1);
    float z = __ldg(cp + 2);

    float scale = P.scale[level];
    int   res   = P.res[level];

    float px = fmaf(x, scale, 0.5f);
    float py = fmaf(y, scale, 0.5f);
    float pz = fmaf(z, scale, 0.5f);
    float gx = floorf(px), gy = floorf(py), gz = floorf(pz);
    float fx = px - gx,    fy = py - gy,    fz = pz - gz;
    int ix = (int)gx, iy = (int)gy, iz = (int)gz;

    const float2* __restrict__ tbl = table + (size_t)level * HASHMAP_SIZE;

    float2 f[8];  // corner i: bit0=x, bit1=y, bit2=z

    if ((P.hashed >> level) & 1u) {
        unsigned hx = (unsigned)ix;
        unsigned hy0 = (unsigned)iy * PRIME_Y, hy1 = hy0 + PRIME_Y;
        unsigned hz0 = (unsigned)iz * PRIME_Z, hz1 = hz0 + PRIME_Z;
        unsigned sv[4] = {hy0 ^ hz0, hy1 ^ hz0, hy0 ^ hz1, hy1 ^ hz1};

        if ((hx & 1u) == 0u) {
            // x even: h(x+1) = h(x)^1 -> aligned 16B entry pair, one LDG.128
            #pragma unroll
            for (int j = 0; j < 4; j++) {
                unsigned u = (hx ^ sv[j]) & HASH_MASK;
                float4 v = __ldg((const float4*)(tbl + (u & ~1u)));
                float2 lo = make_float2(v.x, v.y);
                float2 hi = make_float2(v.z, v.w);
                bool odd = (u & 1u) != 0u;
                f[2*j]     = odd ? hi : lo;
                f[2*j + 1] = odd ? lo : hi;
            }
        } else {
            unsigned hx1 = hx + 1u;
            #pragma unroll
            for (int j = 0; j < 4; j++) {
                f[2*j]     = __ldg(tbl + ((hx  ^ sv[j]) & HASH_MASK));
                f[2*j + 1] = __ldg(tbl + ((hx1 ^ sv[j]) & HASH_MASK));
            }
        }
    } else {
        int rm = res - 1;
        int r2 = res * res;
        int x0 = min(max(ix,     0), rm);
        int x1 = min(max(ix + 1, 0), rm);
        int yb0 = min(max(iy,     0), rm) * res;
        int yb1 = min(max(iy + 1, 0), rm) * res;
        int zb0 = min(max(iz,     0), rm) * r2;
        int zb1 = min(max(iz + 1, 0), rm) * r2;
        int yz[4] = {yb0 + zb0, yb1 + zb0, yb0 + zb1, yb1 + zb1};
        bool adj = (x1 == x0 + 1);
        #pragma unroll
        for (int j = 0; j < 4; j++) {
            int i0 = x0 + yz[j];
            if (adj && ((i0 & 1) == 0)) {
                float4 v = __ldg((const float4*)(tbl + i0));
                f[2*j]     = make_float2(v.x, v.y);
                f[2*j + 1] = make_float2(v.z, v.w);
            } else {
                f[2*j]     = __ldg(tbl + i0);
                f[2*j + 1] = __ldg(tbl + (x1 + yz[j]));
            }
        }
    }

    float wx0 = 1.0f - fx, wy0 = 1.0f - fy, wz0 = 1.0f - fz;
    float s0 = 0.0f, s1 = 0.0f;
    #pragma unroll
    for (int i = 0; i < 8; i++) {
        float w = ((i & 1) ? fx : wx0) * ((i & 2) ? fy : wy0) * ((i & 4) ? fz : wz0);
        s0 = fmaf(w, f[i].x, s0);
        s1 = fmaf(w, f[i].y, s1);
    }

    out[(size_t)p * NUM_LEVELS + level] = make_float2(s0, s1);
}

// ---------------- Kernel B: levels 0..1 staged in shared memory ----------------
__device__ __forceinline__ float2 dense_interp_smem(
    const float2* __restrict__ s_tbl, float x, float y, float z, float scale, int res)
{
    float px = fmaf(x, scale, 0.5f);
    float py = fmaf(y, scale, 0.5f);
    float pz = fmaf(z, scale, 0.5f);
    float gx = floorf(px), gy = floorf(py), gz = floorf(pz);
    float fx = px - gx,    fy = py - gy,    fz = pz - gz;
    int ix = (int)gx, iy = (int)gy, iz = (int)gz;

    int rm = res - 1;
    int r2 = res * res;
    int x0 = min(max(ix,     0), rm);
    int x1 = min(max(ix + 1, 0), rm);
    int yb0 = min(max(iy,     0), rm) * res;
    int yb1 = min(max(iy + 1, 0), rm) * res;
    int zb0 = min(max(iz,     0), rm) * r2;
    int zb1 = min(max(iz + 1, 0), rm) * r2;

    float2 f000 = s_tbl[x0 + yb0 + zb0];
    float2 f100 = s_tbl[x1 + yb0 + zb0];
    float2 f010 = s_tbl[x0 + yb1 + zb0];
    float2 f110 = s_tbl[x1 + yb1 + zb0];
    float2 f001 = s_tbl[x0 + yb0 + zb1];
    float2 f101 = s_tbl[x1 + yb0 + zb1];
    float2 f011 = s_tbl[x0 + yb1 + zb1];
    float2 f111 = s_tbl[x1 + yb1 + zb1];

    float wx0 = 1.0f - fx, wy0 = 1.0f - fy, wz0 = 1.0f - fz;
    float s0 = 0.0f, s1 = 0.0f;
    float w;
    w = wx0*wy0*wz0; s0 = fmaf(w, f000.x, s0); s1 = fmaf(w, f000.y, s1);
    w = fx *wy0*wz0; s0 = fmaf(w, f100.x, s0); s1 = fmaf(w, f100.y, s1);
    w = wx0*fy *wz0; s0 = fmaf(w, f010.x, s0); s1 = fmaf(w, f010.y, s1);
    w = fx *fy *wz0; s0 = fmaf(w, f110.x, s0); s1 = fmaf(w, f110.y, s1);
    w = wx0*wy0*fz ; s0 = fmaf(w, f001.x, s0); s1 = fmaf(w, f001.y, s1);
    w = fx *wy0*fz ; s0 = fmaf(w, f101.x, s0); s1 = fmaf(w, f101.y, s1);
    w = wx0*fy *fz ; s0 = fmaf(w, f011.x, s0); s1 = fmaf(w, f011.y, s1);
    w = fx *fy *fz ; s0 = fmaf(w, f111.x, s0); s1 = fmaf(w, f111.y, s1);
    return make_float2(s0, s1);
}

__global__ void __launch_bounds__(1024) hashgrid_lower_kernel(
    const float* __restrict__ coords,
    const float2* __restrict__ table,
    float2* __restrict__ out,
    int n_points,
    float scale0, int res0, float scale1, int res1)
{
    extern __shared__ float2 s_tbl[];
    int n0 = res0 * res0 * res0;
    int n1 = res1 * res1 * res1;

    for (int i = threadIdx.x; i < n0; i += blockDim.x)
        s_tbl[i] = table[i];
    const float2* t1 = table + HASHMAP_SIZE;
    for (int i = threadIdx.x; i < n1; i += blockDim.x)
        s_tbl[n0 + i] = t1[i];
    __syncthreads();

    int stride = gridDim.x * blockDim.x;
    for (int p = blockIdx.x * blockDim.x + threadIdx.x; p < n_points; p += stride) {
        const float* cp = coords + (size_t)p * 3;
        float x = __ldg(cp + 0);
        float y = __ldg(cp + 1);
        float z = __ldg(cp + 2);

        float2 r0 = dense_interp_smem(s_tbl,      x, y, z, scale0, res0);
        float2 r1 = dense_interp_smem(s_tbl + n0, x, y, z, scale1, res1);

        // levels 0,1 are adjacent float2s at the front of the point's row
        reinterpret_cast<float4*>(out)[(size_t)p * (NUM_LEVELS / 2)] =
            make_float4(r0.x, r0.y, r1.x, r1.y);
    }
}

extern "C" void kernel_launch(void* const* d_in, const int* in_sizes, int n_in,
                              void* d_out, int out_size)
{
    const float*  coords = (const float*)d_in[0];
    const float2* table  = (const float2*)d_in[1];
    float2*       out    = (float2*)d_out;
    int n_points = in_sizes[0] / 3;

    Params P;
    const double l2s = log2(1.3819);
    unsigned hashed = 0;
    for (int l = 0; l < NUM_LEVELS; l++) {
        double scale = exp2((double)l * l2s) * 16.0 - 1.0;
        int res = (int)ceil(scale) + 1;
        P.scale[l] = (float)scale;
        P.res[l]   = res;
        if ((long long)res * res * res > (long long)HASHMAP_SIZE) hashed |= (1u << l);
    }
    P.hashed = hashed;

    // Kernel B: levels 0 and 1 staged in shared memory
    int n0 = P.res[0] * P.res[0] * P.res[0];
    int n1 = P.res[1] * P.res[1] * P.res[1];
    int smem_bytes = (n0 + n1) * (int)sizeof(float2);
    cudaFuncSetAttribute(hashgrid_lower_kernel,
                         cudaFuncAttributeMaxDynamicSharedMemorySize,
                         smem_bytes);
    hashgrid_lower_kernel<<<148, 1024, smem_bytes>>>(
        coords, table, out, n_points, P.scale[0], P.res[0], P.scale[1], P.res[1]);

    // Kernel A: levels 2..15
    long long total = (long long)n_points * NUM_LEVELS;
    long long blocks = (total + 255) / 256;
    hashgrid_upper_kernel<<<(int)blocks, 256>>>(coords, table, out, n_points, P);
}